// round 1
// baseline (speedup 1.0000x reference)
#include <cuda_runtime.h>
#include <math.h>

#define MOBJ 36
#define OBJ  10
#define NPL  16
#define WARPS 8

__device__ __forceinline__ float plinf(const float* __restrict__ wn,
                                       const float* __restrict__ wc,
                                       float x) {
    float y = 16.0f * x;
    int idx = (int)y;                 // trunc toward zero, x >= 0
    float f = y - (float)idx;
    int i0 = idx < NPL ? idx : NPL;
    int i1 = (idx + 1) < NPL ? (idx + 1) : NPL;
    return wc[i0] + f * wn[i1];
}

__device__ __forceinline__ float warp_sum(float v) {
#pragma unroll
    for (int o = 16; o; o >>= 1) v += __shfl_xor_sync(0xffffffffu, v, o);
    return v;
}

__global__ __launch_bounds__(WARPS * 32)
void counter_kernel(const float* __restrict__ boxes,
                    const float* __restrict__ attn,
                    const float* __restrict__ ws,
                    float* __restrict__ out, int n) {
    __shared__ float wn[8][NPL + 1], wc[8][NPL + 1];
    __shared__ float s_att[WARPS][OBJ];
    __shared__ int   s_sel[WARPS][OBJ];
    __shared__ float s_box[WARPS][4][OBJ];
    __shared__ float s_dedup[WARPS][OBJ * OBJ];
    __shared__ float s_score[WARPS][OBJ * OBJ];
    __shared__ float s_sim[WARPS][OBJ * OBJ];
    __shared__ float s_rs[WARPS][OBJ];

    const int tid = threadIdx.x;

    // Normalize the 8 piecewise-lin weight sets once per block.
    if (tid < 8) {
        float tmp[NPL + 1];
        float s = 0.0f;
#pragma unroll
        for (int k = 0; k <= NPL; k++) { tmp[k] = fabsf(ws[tid * (NPL + 1) + k]); s += tmp[k]; }
        float inv = 1.0f / s;
        float c = 0.0f;
#pragma unroll
        for (int k = 0; k <= NPL; k++) {
            float v = tmp[k] * inv;
            wn[tid][k] = v;
            c += v;
            wc[tid][k] = c;
        }
    }
    __syncthreads();

    const int warp = tid >> 5, lane = tid & 31;
    const int row = blockIdx.x * WARPS + warp;
    if (row >= n) return;

    // ---- top-10 of 36 attention values (warp argmax x10) ----
    const float NEG = -3.0e38f;
    float v0 = (lane < MOBJ) ? attn[row * MOBJ + lane] : NEG;
    float v1 = (lane + 32 < MOBJ) ? attn[row * MOBJ + lane + 32] : NEG;
    for (int k = 0; k < OBJ; k++) {
        float lv; int li;
        if (v1 > v0) { lv = v1; li = lane + 32; } else { lv = v0; li = lane; }
#pragma unroll
        for (int o = 16; o; o >>= 1) {
            float ov = __shfl_xor_sync(0xffffffffu, lv, o);
            int   oi = __shfl_xor_sync(0xffffffffu, li, o);
            if (ov > lv || (ov == lv && oi < li)) { lv = ov; li = oi; }
        }
        if (lane == 0) {
            s_att[warp][k] = 1.0f / (1.0f + expf(-lv));   // sigmoid
            s_sel[warp][k] = li;
        }
        if (li == lane) v0 = NEG;
        else if (li == lane + 32) v1 = NEG;
    }
    __syncwarp();

    // ---- gather boxes for selected objects ----
    for (int t = lane; t < 4 * OBJ; t += 32) {
        int c = t / OBJ, o = t % OBJ;
        s_box[warp][c][o] = boxes[(row * 4 + c) * MOBJ + s_sel[warp][o]];
    }
    __syncwarp();

    // ---- pair stage: iou/dist, score, dedup, dist_conf accumulation ----
    float dconf = 0.0f;
    for (int p = lane; p < OBJ * OBJ; p += 32) {
        int b = p / OBJ, c = p % OBJ;
        float ax0 = s_box[warp][0][b], ay0 = s_box[warp][1][b];
        float ax1 = s_box[warp][2][b], ay1 = s_box[warp][3][b];
        float bx0 = s_box[warp][0][c], by0 = s_box[warp][1][c];
        float bx1 = s_box[warp][2][c], by1 = s_box[warp][3][c];
        float iw = fmaxf(fminf(ax1, bx1) - fmaxf(ax0, bx0), 0.0f);
        float ih = fmaxf(fminf(ay1, by1) - fmaxf(ay0, by0), 0.0f);
        float inter = iw * ih;
        float aa = fmaxf(ax1 - ax0, 0.0f) * fmaxf(ay1 - ay0, 0.0f);
        float ab = fmaxf(bx1 - bx0, 0.0f) * fmaxf(by1 - by0, 0.0f);
        float iou = inter / (aa + ab - inter + 1e-12f);
        float dist = 1.0f - iou;
        float relev = s_att[warp][b] * s_att[warp][c];
        s_score[warp][p] = plinf(wn[0], wc[0], relev) * plinf(wn[1], wc[1], dist);
        s_dedup[warp][p] = plinf(wn[3], wc[3], relev) * plinf(wn[4], wc[4], dist);
        dconf += fabsf(plinf(wn[6], wc[6], dist) - 0.5f);
    }
    __syncwarp();

    // ---- sim[b][c] = prod_a plin2(1-|dedup[a][b]-dedup[a][c]|) * plin2(1-|att[b]-att[c]|) ----
    for (int p = lane; p < OBJ * OBJ; p += 32) {
        int b = p / OBJ, c = p % OBJ;
        float prod = plinf(wn[2], wc[2], 1.0f - fabsf(s_att[warp][b] - s_att[warp][c]));
#pragma unroll
        for (int a = 0; a < OBJ; a++) {
            float d = fabsf(s_dedup[warp][a * OBJ + b] - s_dedup[warp][a * OBJ + c]);
            prod *= plinf(wn[2], wc[2], 1.0f - d);
        }
        s_sim[warp][p] = prod;
    }
    __syncwarp();

    // ---- row sims, correction, att_conf ----
    float corr = 0.0f, aconf = 0.0f;
    if (lane < OBJ) {
        float rs = 0.0f;
#pragma unroll
        for (int c = 0; c < OBJ; c++) rs += s_sim[warp][lane * OBJ + c];
        s_rs[warp][lane] = rs;
        float a = s_att[warp][lane];
        corr = plinf(wn[0], wc[0], a * a) / rs;
        aconf = fabsf(plinf(wn[5], wc[5], a) - 0.5f);
    }
    __syncwarp();

    // ---- score / all_sims sum ----
    float ssum = 0.0f;
    for (int p = lane; p < OBJ * OBJ; p += 32) {
        int b = p / OBJ, c = p % OBJ;
        ssum += s_score[warp][p] / (s_rs[warp][b] * s_rs[warp][c]);
    }

    float tot = warp_sum(ssum + corr);
    tot = sqrtf(tot + 1e-20f);
    float confarg = warp_sum(aconf) * (1.0f / OBJ) + warp_sum(dconf) * (1.0f / (OBJ * OBJ));
    float conf = plinf(wn[7], wc[7], confarg);

    // ---- one-hot interpolation * conf ----
    float s = fminf(fmaxf(tot, 0.0f), (float)OBJ);
    int i = (int)s;
    float f = s - (float)i;
    int i0 = i < OBJ ? i : OBJ;
    int i1 = (i + 1) < OBJ ? (i + 1) : OBJ;
    if (lane < OBJ + 1) {
        float v = 0.0f;
        if (lane == i0) v += 1.0f - f;
        if (lane == i1) v += f;
        out[row * (OBJ + 1) + lane] = v * conf;
    }
}

extern "C" void kernel_launch(void* const* d_in, const int* in_sizes, int n_in,
                              void* d_out, int out_size) {
    const float* boxes = (const float*)d_in[0];
    const float* attn  = (const float*)d_in[1];
    const float* ws    = (const float*)d_in[2];
    float* out = (float*)d_out;
    int n = in_sizes[0] / (4 * MOBJ);
    int blocks = (n + WARPS - 1) / WARPS;
    counter_kernel<<<blocks, WARPS * 32>>>(boxes, attn, ws, out, n);
}

// round 4
// speedup vs baseline: 1.5634x; 1.5634x over previous
#include <cuda_runtime.h>
#include <math.h>

#define MOBJ 36
#define OBJ  10
#define NPL  16
#define WARPS 8
#define NPAIR 45   // strict upper triangle of 10x10

// Fused piecewise-lin lookup: t[i] = (csum[i], w[min(i+1,16)]), one LDS.64.
__device__ __forceinline__ float plin2f(const float2* __restrict__ t, float x) {
    float y = 16.0f * x;
    int idx = (int)y;
    idx = idx < NPL ? idx : NPL;
    float f = y - (float)idx;
    float2 v = t[idx];
    return fmaf(f, v.y, v.x);
}

__device__ __forceinline__ float warp_sum(float v) {
#pragma unroll
    for (int o = 16; o; o >>= 1) v += __shfl_xor_sync(0xffffffffu, v, o);
    return v;
}

__global__ __launch_bounds__(WARPS * 32)
void counter_kernel(const float* __restrict__ boxes,
                    const float* __restrict__ attn,
                    const float* __restrict__ ws,
                    float* __restrict__ out, int n) {
    __shared__ float2 tab[8][NPL + 1];
    __shared__ unsigned char s_pb[NPAIR + 3], s_pc[NPAIR + 3];
    __shared__ float s_att[WARPS][OBJ];
    __shared__ int   s_sel[WARPS][OBJ];
    __shared__ float s_box[WARPS][4][OBJ];
    __shared__ float s_dedup[WARPS][OBJ * OBJ];
    __shared__ float s_sc[WARPS][NPAIR];        // upper-tri score only
    __shared__ float s_scd[WARPS][OBJ];         // diagonal score
    __shared__ float s_sim[WARPS][OBJ * OBJ];
    __shared__ float s_ri[WARPS][OBJ];          // 1/row_sims
    __shared__ float s_p0[WARPS][OBJ];          // plin0(att^2)

    const int tid = threadIdx.x;

    // Normalize the 8 weight sets into fused (lo, hi) tables.
    if (tid < 8) {
        float tmp[NPL + 1];
        float s = 0.0f;
#pragma unroll
        for (int k = 0; k <= NPL; k++) { tmp[k] = fabsf(ws[tid * (NPL + 1) + k]); s += tmp[k]; }
        float inv = 1.0f / s;
        float c = 0.0f;
        float wnorm[NPL + 1];
#pragma unroll
        for (int k = 0; k <= NPL; k++) { wnorm[k] = tmp[k] * inv; }
#pragma unroll
        for (int k = 0; k <= NPL; k++) {
            c += wnorm[k];
            int k1 = (k + 1) < NPL ? (k + 1) : NPL;
            tab[tid][k] = make_float2(c, wnorm[k1]);
        }
    }
    // Pair map: p -> (b, c), b < c.
    if (tid < NPAIR) {
        int p = tid, b = 0;
        while (p >= 9 - b) { p -= 9 - b; b++; }
        s_pb[tid] = (unsigned char)b;
        s_pc[tid] = (unsigned char)(b + 1 + p);
    }
    __syncthreads();

    const int warp = tid >> 5, lane = tid & 31;
    const int row = blockIdx.x * WARPS + warp;
    if (row >= n) return;

    // ---- top-10 of 36 (warp argmax x10) ----
    const float NEG = -3.0e38f;
    float v0 = (lane < MOBJ) ? attn[row * MOBJ + lane] : NEG;
    float v1 = (lane + 32 < MOBJ) ? attn[row * MOBJ + lane + 32] : NEG;
    for (int k = 0; k < OBJ; k++) {
        float lv; int li;
        if (v1 > v0) { lv = v1; li = lane + 32; } else { lv = v0; li = lane; }
#pragma unroll
        for (int o = 16; o; o >>= 1) {
            float ov = __shfl_xor_sync(0xffffffffu, lv, o);
            int   oi = __shfl_xor_sync(0xffffffffu, li, o);
            if (ov > lv || (ov == lv && oi < li)) { lv = ov; li = oi; }
        }
        if (lane == 0) {
            s_att[warp][k] = __fdividef(1.0f, 1.0f + __expf(-lv));
            s_sel[warp][k] = li;
        }
        if (li == lane) v0 = NEG;
        else if (li == lane + 32) v1 = NEG;
    }
    __syncwarp();

    // ---- gather boxes ----
    for (int t = lane; t < 4 * OBJ; t += 32) {
        int c = t / OBJ, o = t % OBJ;
        s_box[warp][c][o] = boxes[(row * 4 + c) * MOBJ + s_sel[warp][o]];
    }
    __syncwarp();

    const float P2one = tab[2][NPL].x;                 // plin2(1.0) (== 1 after norm)

    // ---- pair stage (45 upper pairs + 10 diagonal) ----
    float dconf = 0.0f;
#pragma unroll
    for (int r = 0; r < 2; r++) {
        int p = lane + r * 32;
        if (p < NPAIR) {
            int b = s_pb[p], c = s_pc[p];
            float ax0 = s_box[warp][0][b], ay0 = s_box[warp][1][b];
            float ax1 = s_box[warp][2][b], ay1 = s_box[warp][3][b];
            float bx0 = s_box[warp][0][c], by0 = s_box[warp][1][c];
            float bx1 = s_box[warp][2][c], by1 = s_box[warp][3][c];
            float iw = fmaxf(fminf(ax1, bx1) - fmaxf(ax0, bx0), 0.0f);
            float ih = fmaxf(fminf(ay1, by1) - fmaxf(ay0, by0), 0.0f);
            float inter = iw * ih;
            float aa = fmaxf(ax1 - ax0, 0.0f) * fmaxf(ay1 - ay0, 0.0f);
            float ab = fmaxf(bx1 - bx0, 0.0f) * fmaxf(by1 - by0, 0.0f);
            float dist = 1.0f - __fdividef(inter, aa + ab - inter + 1e-12f);
            float relev = s_att[warp][b] * s_att[warp][c];
            s_sc[warp][p] = plin2f(tab[0], relev) * plin2f(tab[1], dist);
            float dd = plin2f(tab[3], relev) * plin2f(tab[4], dist);
            s_dedup[warp][b * OBJ + c] = dd;
            s_dedup[warp][c * OBJ + b] = dd;
            dconf += 2.0f * fabsf(plin2f(tab[6], dist) - 0.5f);
        }
    }
    // Diagonal: dist_d = 1 - area/(area + 1e-12). NOT ~0: random boxes are
    // often degenerate (area==0 -> dist_d==1).
    float aconf = 0.0f;
    if (lane < OBJ) {
        float a = s_att[warp][lane];
        float aa = fmaxf(s_box[warp][2][lane] - s_box[warp][0][lane], 0.0f)
                 * fmaxf(s_box[warp][3][lane] - s_box[warp][1][lane], 0.0f);
        float dist_d = 1.0f - __fdividef(aa, aa + 1e-12f);
        float relev = a * a;
        float p0 = plin2f(tab[0], relev);
        s_p0[warp][lane] = p0;
        s_scd[warp][lane] = p0 * plin2f(tab[1], dist_d);
        s_dedup[warp][lane * (OBJ + 1)] = plin2f(tab[3], relev) * plin2f(tab[4], dist_d);
        dconf += fabsf(plin2f(tab[6], dist_d) - 0.5f);
        aconf = fabsf(plin2f(tab[5], a) - 0.5f);
    }
    __syncwarp();

    // ---- sim (upper pairs; diagonal = plin2(1)^11, dist-independent) ----
#pragma unroll
    for (int r = 0; r < 2; r++) {
        int p = lane + r * 32;
        if (p < NPAIR) {
            int b = s_pb[p], c = s_pc[p];
            const float* db = &s_dedup[warp][b];
            const float* dc = &s_dedup[warp][c];
            float prod = plin2f(tab[2], 1.0f - fabsf(s_att[warp][b] - s_att[warp][c]));
#pragma unroll
            for (int a = 0; a < OBJ; a++) {
                float d = fabsf(db[a * OBJ] - dc[a * OBJ]);
                prod *= plin2f(tab[2], 1.0f - d);
            }
            s_sim[warp][b * OBJ + c] = prod;
            s_sim[warp][c * OBJ + b] = prod;
        }
    }
    if (lane < OBJ) {
        float sd = P2one;
#pragma unroll
        for (int a = 0; a < OBJ; a++) sd *= P2one;     // P2one^11
        s_sim[warp][lane * (OBJ + 1)] = sd;
    }
    __syncwarp();

    // ---- row sims -> reciprocals, correction ----
    float corr = 0.0f;
    if (lane < OBJ) {
        float rs = 0.0f;
#pragma unroll
        for (int c = 0; c < OBJ; c++) rs += s_sim[warp][lane * OBJ + c];
        float ri = __fdividef(1.0f, rs);
        s_ri[warp][lane] = ri;
        corr = s_p0[warp][lane] * ri;
    }
    __syncwarp();

    // ---- score / all_sims sum (2x upper + diag) ----
    float ssum = 0.0f;
#pragma unroll
    for (int r = 0; r < 2; r++) {
        int p = lane + r * 32;
        if (p < NPAIR) {
            int b = s_pb[p], c = s_pc[p];
            ssum += 2.0f * s_sc[warp][p] * s_ri[warp][b] * s_ri[warp][c];
        }
    }
    if (lane < OBJ) {
        float ri = s_ri[warp][lane];
        ssum += s_scd[warp][lane] * ri * ri;           // diagonal score term
    }

    float tot = sqrtf(warp_sum(ssum + corr) + 1e-20f);
    float confarg = warp_sum(aconf * (1.0f / OBJ) + dconf * (1.0f / (OBJ * OBJ)));
    float conf = plin2f(tab[7], confarg);

    // ---- one-hot * conf ----
    float s = fminf(fmaxf(tot, 0.0f), (float)OBJ);
    int i = (int)s;
    float f = s - (float)i;
    int i0 = i < OBJ ? i : OBJ;
    int i1 = (i + 1) < OBJ ? (i + 1) : OBJ;
    if (lane < OBJ + 1) {
        float v = 0.0f;
        if (lane == i0) v += 1.0f - f;
        if (lane == i1) v += f;
        out[row * (OBJ + 1) + lane] = v * conf;
    }
}

extern "C" void kernel_launch(void* const* d_in, const int* in_sizes, int n_in,
                              void* d_out, int out_size) {
    const float* boxes = (const float*)d_in[0];
    const float* attn  = (const float*)d_in[1];
    const float* ws    = (const float*)d_in[2];
    float* out = (float*)d_out;
    int n = in_sizes[0] / (4 * MOBJ);
    int blocks = (n + WARPS - 1) / WARPS;
    counter_kernel<<<blocks, WARPS * 32>>>(boxes, attn, ws, out, n);
}

// round 5
// speedup vs baseline: 1.7362x; 1.1105x over previous
#include <cuda_runtime.h>
#include <math.h>

#define MOBJ 36
#define OBJ  10
#define NPL  16
#define WARPS 8
#define NITEM 55   // upper triangle incl. diagonal of 10x10

#define PLMAGIC  12582912.0f   // 1.5 * 2^23
#define PLMAGICI 0x4B400000u

// Piecewise-lin lookup, y = 16*x precomputed, y in [0,16].
// Round-down magic add: floor in float and int form without F2I/I2F/IMIN.
__device__ __forceinline__ float plin_y(const float2* __restrict__ t, float y) {
    float z = __fadd_rd(y, PLMAGIC);
    int idx = (int)(__float_as_uint(z) - PLMAGICI);
    float f = y - (z - PLMAGIC);
    float2 v = t[idx];
    return fmaf(f, v.y, v.x);
}
__device__ __forceinline__ float plin_x(const float2* __restrict__ t, float x) {
    return plin_y(t, 16.0f * x);
}

__device__ __forceinline__ float warp_sum(float v) {
#pragma unroll
    for (int o = 16; o; o >>= 1) v += __shfl_xor_sync(0xffffffffu, v, o);
    return v;
}

__global__ __launch_bounds__(WARPS * 32)
void counter_kernel(const float* __restrict__ boxes,
                    const float* __restrict__ attn,
                    const float* __restrict__ ws,
                    float* __restrict__ out, int n) {
    __shared__ float2 tab[8][NPL + 1];
    __shared__ unsigned char s_pb[NITEM + 1], s_pc[NITEM + 1];
    __shared__ float  s_att[WARPS][OBJ];
    __shared__ int    s_sel[WARPS][OBJ];
    __shared__ float4 s_box[WARPS][OBJ];
    __shared__ float  s_dedup[WARPS][OBJ * OBJ];
    __shared__ float  s_sc[WARPS][NITEM];
    __shared__ float  s_sim[WARPS][OBJ * OBJ];
    __shared__ float  s_ri[WARPS][OBJ];
    __shared__ float  s_p0[WARPS][OBJ];

    const int tid = threadIdx.x;

    // Normalize the 8 weight sets into fused (csum, w[min(i+1,16)]) tables.
    if (tid < 8) {
        float tmp[NPL + 1];
        float s = 0.0f;
#pragma unroll
        for (int k = 0; k <= NPL; k++) { tmp[k] = fabsf(ws[tid * (NPL + 1) + k]); s += tmp[k]; }
        float inv = 1.0f / s;
        float c = 0.0f;
#pragma unroll
        for (int k = 0; k <= NPL; k++) {
            float v = tmp[k] * inv;
            c += v;
            int k1 = (k + 1) < NPL ? (k + 1) : NPL;
            tab[tid][k] = make_float2(c, tmp[k1] * inv);
        }
    }
    // Item map: p -> (b, c), b <= c.
    if (tid < NITEM) {
        int p = tid, b = 0;
        while (p >= OBJ - b) { p -= OBJ - b; b++; }
        s_pb[tid] = (unsigned char)b;
        s_pc[tid] = (unsigned char)(b + p);
    }
    __syncthreads();

    const int warp = tid >> 5, lane = tid & 31;
    const int row = blockIdx.x * WARPS + warp;
    if (row >= n) return;

    // ---- top-10 of 36 (warp argmax x10), raw values stored ----
    const float NEG = -3.0e38f;
    float v0 = (lane < MOBJ) ? attn[row * MOBJ + lane] : NEG;
    float v1 = (lane + 32 < MOBJ) ? attn[row * MOBJ + lane + 32] : NEG;
    for (int k = 0; k < OBJ; k++) {
        float lv; int li;
        if (v1 > v0) { lv = v1; li = lane + 32; } else { lv = v0; li = lane; }
#pragma unroll
        for (int o = 16; o; o >>= 1) {
            float ov = __shfl_xor_sync(0xffffffffu, lv, o);
            int   oi = __shfl_xor_sync(0xffffffffu, li, o);
            if (ov > lv || (ov == lv && oi < li)) { lv = ov; li = oi; }
        }
        if (lane == 0) { s_att[warp][k] = lv; s_sel[warp][k] = li; }
        if (li == lane) v0 = NEG;
        else if (li == lane + 32) v1 = NEG;
    }
    __syncwarp();

    // ---- gather boxes (float4 per object) + sigmoid + aconf ----
#pragma unroll
    for (int r = 0; r < 2; r++) {
        int t = lane + r * 32;
        if (t < 4 * OBJ) {
            int o = t >> 2, c = t & 3;
            ((float*)&s_box[warp][0])[o * 4 + c] =
                boxes[(row * 4 + c) * MOBJ + s_sel[warp][o]];
        }
    }
    float aconf = 0.0f;
    if (lane < OBJ) {
        float a = __fdividef(1.0f, 1.0f + __expf(-s_att[warp][lane]));
        s_att[warp][lane] = a;
        aconf = fabsf(plin_x(tab[5], a) - 0.5f);
    }
    __syncwarp();

    // ---- pair stage: 55 items (b<=c), general code valid on diagonal ----
    float dconf = 0.0f;
#pragma unroll
    for (int r = 0; r < 2; r++) {
        int p = lane + r * 32;
        if (p < NITEM) {
            int b = s_pb[p], c = s_pc[p];
            float4 B = s_box[warp][b], C = s_box[warp][c];
            float iw = fmaxf(fminf(B.z, C.z) - fmaxf(B.x, C.x), 0.0f);
            float ih = fmaxf(fminf(B.w, C.w) - fmaxf(B.y, C.y), 0.0f);
            float inter = iw * ih;
            float aa = fmaxf(B.z - B.x, 0.0f) * fmaxf(B.w - B.y, 0.0f);
            float ab = fmaxf(C.z - C.x, 0.0f) * fmaxf(C.w - C.y, 0.0f);
            float dist = fmaxf(1.0f - __fdividef(inter, aa + ab - inter + 1e-12f), 0.0f);
            float relev = s_att[warp][b] * s_att[warp][c];
            float p0 = plin_x(tab[0], relev);
            s_sc[warp][p] = p0 * plin_x(tab[1], dist);
            float dd = plin_x(tab[3], relev) * plin_x(tab[4], dist);
            s_dedup[warp][b * OBJ + c] = dd;
            s_dedup[warp][c * OBJ + b] = dd;
            float fac = (b == c) ? 1.0f : 2.0f;
            dconf += fac * fabsf(plin_x(tab[6], dist) - 0.5f);
            if (b == c) s_p0[warp][b] = p0;
        }
    }
    __syncwarp();

    // ---- sim: 55 items; diagonal handled by the same code (|d|=0) ----
#pragma unroll
    for (int r = 0; r < 2; r++) {
        int p = lane + r * 32;
        if (p < NITEM) {
            int b = s_pb[p], c = s_pc[p];
            const float* db = &s_dedup[warp][b];
            const float* dc = &s_dedup[warp][c];
            float da = s_att[warp][b] - s_att[warp][c];
            float prod = plin_y(tab[2], fmaf(-16.0f, fabsf(da), 16.0f));
#pragma unroll
            for (int a = 0; a < OBJ; a++) {
                float d = db[a * OBJ] - dc[a * OBJ];
                prod *= plin_y(tab[2], fmaf(-16.0f, fabsf(d), 16.0f));
            }
            s_sim[warp][b * OBJ + c] = prod;
            s_sim[warp][c * OBJ + b] = prod;
        }
    }
    __syncwarp();

    // ---- row sims -> reciprocals, correction ----
    float corr = 0.0f;
    if (lane < OBJ) {
        float rs = 0.0f;
#pragma unroll
        for (int c = 0; c < OBJ; c++) rs += s_sim[warp][lane * OBJ + c];
        float ri = __fdividef(1.0f, rs);
        s_ri[warp][lane] = ri;
        corr = s_p0[warp][lane] * ri;
    }
    __syncwarp();

    // ---- score / all_sims sum ----
    float ssum = 0.0f;
#pragma unroll
    for (int r = 0; r < 2; r++) {
        int p = lane + r * 32;
        if (p < NITEM) {
            int b = s_pb[p], c = s_pc[p];
            float fac = (b == c) ? 1.0f : 2.0f;
            ssum += fac * s_sc[warp][p] * s_ri[warp][b] * s_ri[warp][c];
        }
    }

    float tot = sqrtf(warp_sum(ssum + corr) + 1e-20f);
    float confarg = warp_sum(aconf * (1.0f / OBJ) + dconf * (1.0f / (OBJ * OBJ)));
    float conf = plin_x(tab[7], confarg);

    // ---- one-hot * conf ----
    float s = fminf(fmaxf(tot, 0.0f), (float)OBJ);
    int i = (int)s;
    float f = s - (float)i;
    int i0 = i < OBJ ? i : OBJ;
    int i1 = (i + 1) < OBJ ? (i + 1) : OBJ;
    if (lane < OBJ + 1) {
        float v = 0.0f;
        if (lane == i0) v += 1.0f - f;
        if (lane == i1) v += f;
        out[row * (OBJ + 1) + lane] = v * conf;
    }
}

extern "C" void kernel_launch(void* const* d_in, const int* in_sizes, int n_in,
                              void* d_out, int out_size) {
    const float* boxes = (const float*)d_in[0];
    const float* attn  = (const float*)d_in[1];
    const float* ws    = (const float*)d_in[2];
    float* out = (float*)d_out;
    int n = in_sizes[0] / (4 * MOBJ);
    int blocks = (n + WARPS - 1) / WARPS;
    counter_kernel<<<blocks, WARPS * 32>>>(boxes, attn, ws, out, n);
}

// round 7
// speedup vs baseline: 2.2750x; 1.3103x over previous
#include <cuda_runtime.h>
#include <math.h>

#define MOBJ 36
#define OBJ  10
#define NPL  16
#define WARPS 8          // rows per block == warps per block
#define NITEM 55         // upper triangle incl. diagonal of 10x10

#define PLMAGIC  12582912.0f   // 1.5 * 2^23
#define PLMAGICI 0x4B400000u

// floor(y) as small int + fractional part, no F2I/I2F/IMIN (y in [0,16]).
__device__ __forceinline__ void plfloor(float y, int& idx, float& f) {
    float z = __fadd_rd(y, PLMAGIC);
    idx = (int)(__float_as_uint(z) - PLMAGICI);
    f = y - (z - PLMAGIC);
}

__device__ __forceinline__ float plin2t(const float2* __restrict__ t, float y) {
    int idx; float f;
    plfloor(y, idx, f);
    float2 v = t[idx];
    return fmaf(f, v.y, v.x);
}

__device__ __forceinline__ float warp_sum(float v) {
#pragma unroll
    for (int o = 16; o; o >>= 1) v += __shfl_xor_sync(0xffffffffu, v, o);
    return v;
}

__device__ __forceinline__ unsigned long long sortkey(float v, int idx) {
    unsigned int u = __float_as_uint(v);
    u ^= (unsigned int)(((int)u) >> 31) | 0x80000000u;   // monotone map
    return ((unsigned long long)u << 6) | (unsigned long long)(63 - idx);
}

__global__ __launch_bounds__(WARPS * 32)
void counter_kernel(const float* __restrict__ boxes,
                    const float* __restrict__ attn,
                    const float* __restrict__ ws,
                    float* __restrict__ out, int n) {
    __shared__ float4 tabR[NPL + 1];     // {csum0, w0', csum3, w3'}
    __shared__ float4 tabD[NPL + 1];     // {csum1, w1', csum4, w4'}
    __shared__ float2 tabD6[NPL + 1];    // {csum6, w6'}
    __shared__ float2 tab2[NPL + 1], tab5[NPL + 1], tab7[NPL + 1];
    __shared__ unsigned char s_pb[NITEM + 1], s_pc[NITEM + 1];
    __shared__ unsigned long long s_key[WARPS][MOBJ];
    __shared__ float  s_att[WARPS][OBJ];
    __shared__ float4 s_box[WARPS][OBJ];
    __shared__ float  s_dedup[WARPS][OBJ * OBJ];
    __shared__ float  s_sc[WARPS][NITEM];
    __shared__ float  s_sim[WARPS][OBJ * OBJ];
    __shared__ float  s_ri[WARPS][OBJ];
    __shared__ float  s_p0[WARPS][OBJ];

    const int tid = threadIdx.x;

    // ---- normalize 8 weight sets into packed fused tables ----
    if (tid < 8) {
        float tmp[NPL + 1];
        float s = 0.0f;
#pragma unroll
        for (int k = 0; k <= NPL; k++) { tmp[k] = fabsf(ws[tid * (NPL + 1) + k]); s += tmp[k]; }
        float inv = 1.0f / s;
        float* bp; int st;
        switch (tid) {
            case 0: bp = &tabR[0].x;  st = 4; break;
            case 3: bp = &tabR[0].z;  st = 4; break;
            case 1: bp = &tabD[0].x;  st = 4; break;
            case 4: bp = &tabD[0].z;  st = 4; break;
            case 6: bp = &tabD6[0].x; st = 2; break;
            case 2: bp = &tab2[0].x;  st = 2; break;
            case 5: bp = &tab5[0].x;  st = 2; break;
            default: bp = &tab7[0].x; st = 2; break;
        }
        float c = 0.0f;
#pragma unroll
        for (int k = 0; k <= NPL; k++) {
            c += tmp[k] * inv;
            int k1 = (k + 1) < NPL ? (k + 1) : NPL;
            bp[k * st]     = c;
            bp[k * st + 1] = tmp[k1] * inv;
        }
    }
    // item map p -> (b,c), b <= c
    if (tid < NITEM) {
        int p = tid, b = 0;
        while (p >= OBJ - b) { p -= OBJ - b; b++; }
        s_pb[tid] = (unsigned char)b;
        s_pc[tid] = (unsigned char)(b + p);
    }

    // ---- block-cooperative top-k via ranks ----
    const int rowbase = blockIdx.x * WARPS;
    const int nv = (n - rowbase) * MOBJ;              // valid value-slots in block
    // primary value: global slot = tid
    int r1 = tid / MOBJ, i1 = tid - r1 * MOBJ;
    float v1 = 0.0f;
    if (tid < nv) v1 = attn[rowbase * MOBJ + tid];    // fully coalesced
    unsigned long long k1 = sortkey(v1, i1);
    s_key[r1][i1] = k1;
    // spare 32 values: slot = tid + 256 -> row 7, idx tid+4
    float v2 = 0.0f;
    unsigned long long k2 = 0;
    if (tid < 32) {
        int sl = tid + WARPS * 32;
        if (sl < nv) v2 = attn[rowbase * MOBJ + sl];
        k2 = sortkey(v2, tid + 4);
        s_key[WARPS - 1][tid + 4] = k2;
    }
    __syncthreads();

    {
        int rk = 0;
#pragma unroll
        for (int j = 0; j < MOBJ; j++) rk += (s_key[r1][j] > k1) ? 1 : 0;
        if (rk < OBJ && tid < nv) {
            float a = __fdividef(1.0f, 1.0f + __expf(-v1));
            s_att[r1][rk] = a;
            const float* bb = boxes + (size_t)(rowbase + r1) * 4 * MOBJ + i1;
            s_box[r1][rk] = make_float4(bb[0], bb[MOBJ], bb[2 * MOBJ], bb[3 * MOBJ]);
        }
    }
    if (tid < 32) {
        int rk = 0;
#pragma unroll
        for (int j = 0; j < MOBJ; j++) rk += (s_key[WARPS - 1][j] > k2) ? 1 : 0;
        if (rk < OBJ && tid + WARPS * 32 < nv) {
            float a = __fdividef(1.0f, 1.0f + __expf(-v2));
            s_att[WARPS - 1][rk] = a;
            const float* bb = boxes + (size_t)(rowbase + WARPS - 1) * 4 * MOBJ + (tid + 4);
            s_box[WARPS - 1][rk] = make_float4(bb[0], bb[MOBJ], bb[2 * MOBJ], bb[3 * MOBJ]);
        }
    }
    __syncthreads();

    const int warp = tid >> 5, lane = tid & 31;
    const int row = rowbase + warp;
    if (row >= n) return;

    // ---- pair stage: 55 items (b<=c); shared floors, packed tables ----
    float dconf = 0.0f;
#pragma unroll
    for (int r = 0; r < 2; r++) {
        int p = lane + r * 32;
        if (p < NITEM) {
            int b = s_pb[p], c = s_pc[p];
            float4 B = s_box[warp][b], C = s_box[warp][c];
            float iw = fmaxf(fminf(B.z, C.z) - fmaxf(B.x, C.x), 0.0f);
            float ih = fmaxf(fminf(B.w, C.w) - fmaxf(B.y, C.y), 0.0f);
            float inter = iw * ih;
            float aa = fmaxf(B.z - B.x, 0.0f) * fmaxf(B.w - B.y, 0.0f);
            float ab = fmaxf(C.z - C.x, 0.0f) * fmaxf(C.w - C.y, 0.0f);
            float dist = fmaxf(1.0f - __fdividef(inter, aa + ab - inter + 1e-12f), 0.0f);
            float relev = s_att[warp][b] * s_att[warp][c];
            int ir; float fr; plfloor(16.0f * relev, ir, fr);
            float4 R = tabR[ir];
            float p0 = fmaf(fr, R.y, R.x);
            float p3 = fmaf(fr, R.w, R.z);
            int id; float fd; plfloor(16.0f * dist, id, fd);
            float4 D = tabD[id];
            float2 D6 = tabD6[id];
            float p1 = fmaf(fd, D.y, D.x);
            float p4 = fmaf(fd, D.w, D.z);
            float p6 = fmaf(fd, D6.y, D6.x);
            s_sc[warp][p] = p0 * p1;
            float dd = p3 * p4;
            s_dedup[warp][b * OBJ + c] = dd;
            s_dedup[warp][c * OBJ + b] = dd;
            float fac = (b == c) ? 1.0f : 2.0f;
            dconf += fac * fabsf(p6 - 0.5f);
            if (b == c) s_p0[warp][b] = p0;
        }
    }
    __syncwarp();

    // ---- sim: 55 items; diagonal handled by same code (|d|=0) ----
#pragma unroll
    for (int r = 0; r < 2; r++) {
        int p = lane + r * 32;
        if (p < NITEM) {
            int b = s_pb[p], c = s_pc[p];
            const float* db = &s_dedup[warp][b];
            const float* dc = &s_dedup[warp][c];
            float da = s_att[warp][b] - s_att[warp][c];
            float prod = plin2t(tab2, fmaf(-16.0f, fabsf(da), 16.0f));
#pragma unroll
            for (int a = 0; a < OBJ; a++) {
                float d = db[a * OBJ] - dc[a * OBJ];
                prod *= plin2t(tab2, fmaf(-16.0f, fabsf(d), 16.0f));
            }
            s_sim[warp][b * OBJ + c] = prod;
            s_sim[warp][c * OBJ + b] = prod;
        }
    }
    __syncwarp();

    // ---- row sims -> reciprocals, correction, aconf ----
    float corr = 0.0f, aconf = 0.0f;
    if (lane < OBJ) {
        float rs = 0.0f;
#pragma unroll
        for (int c = 0; c < OBJ; c++) rs += s_sim[warp][lane * OBJ + c];
        float ri = __fdividef(1.0f, rs);
        s_ri[warp][lane] = ri;
        corr = s_p0[warp][lane] * ri;
        aconf = fabsf(plin2t(tab5, 16.0f * s_att[warp][lane]) - 0.5f);
    }
    __syncwarp();

    // ---- score / all_sims sum ----
    float ssum = 0.0f;
#pragma unroll
    for (int r = 0; r < 2; r++) {
        int p = lane + r * 32;
        if (p < NITEM) {
            int b = s_pb[p], c = s_pc[p];
            float fac = (b == c) ? 1.0f : 2.0f;
            ssum += fac * s_sc[warp][p] * s_ri[warp][b] * s_ri[warp][c];
        }
    }

    float tot = sqrtf(warp_sum(ssum + corr) + 1e-20f);
    float confarg = warp_sum(aconf * (1.0f / OBJ) + dconf * (1.0f / (OBJ * OBJ)));
    float conf = plin2t(tab7, 16.0f * confarg);

    // ---- one-hot * conf ----
    float s = fminf(fmaxf(tot, 0.0f), (float)OBJ);
    int ii = (int)s;
    float f = s - (float)ii;
    int oh0 = ii < OBJ ? ii : OBJ;
    int oh1 = (ii + 1) < OBJ ? (ii + 1) : OBJ;
    if (lane < OBJ + 1) {
        float v = 0.0f;
        if (lane == oh0) v += 1.0f - f;
        if (lane == oh1) v += f;
        out[row * (OBJ + 1) + lane] = v * conf;
    }
}

extern "C" void kernel_launch(void* const* d_in, const int* in_sizes, int n_in,
                              void* d_out, int out_size) {
    const float* boxes = (const float*)d_in[0];
    const float* attn  = (const float*)d_in[1];
    const float* ws    = (const float*)d_in[2];
    float* out = (float*)d_out;
    int n = in_sizes[0] / (4 * MOBJ);
    int blocks = (n + WARPS - 1) / WARPS;
    counter_kernel<<<blocks, WARPS * 32>>>(boxes, attn, ws, out, n);
}

// round 11
// speedup vs baseline: 2.5399x; 1.1165x over previous
#include <cuda_runtime.h>
#include <math.h>

#define MOBJ 36
#define OBJ  10
#define NPL  16
#define WARPS 8          // rows per block == warps per block
#define NITEM 55         // upper triangle incl. diagonal of 10x10
#define DPAD 12          // padded dedup column stride (floats)

#define PLMAGIC  12582912.0f   // 1.5 * 2^23
#define PLMAGICI 0x4B400000u

// floor(y) as small int + fractional part, no F2I/I2F/IMIN (y in [0,16]).
__device__ __forceinline__ void plfloor(float y, int& idx, float& f) {
    float z = __fadd_rd(y, PLMAGIC);
    idx = (int)(__float_as_uint(z) - PLMAGICI);
    f = y - (z - PLMAGIC);
}

__device__ __forceinline__ float plin2t(const float2* __restrict__ t, float y) {
    int idx; float f;
    plfloor(y, idx, f);
    float2 v = t[idx];
    return fmaf(f, v.y, v.x);
}

__device__ __forceinline__ float warp_sum(float v) {
#pragma unroll
    for (int o = 16; o; o >>= 1) v += __shfl_xor_sync(0xffffffffu, v, o);
    return v;
}

// monotone map float -> u32 (order preserving), and inverse
__device__ __forceinline__ unsigned mapf(float v) {
    unsigned u = __float_as_uint(v);
    return u ^ ((unsigned)(((int)u) >> 31) | 0x80000000u);
}
__device__ __forceinline__ float unmapf(unsigned m) {
    unsigned u = (m & 0x80000000u) ? (m ^ 0x80000000u) : ~m;
    return __uint_as_float(u);
}

__global__ __launch_bounds__(WARPS * 32)
void counter_kernel(const float* __restrict__ boxes,
                    const float* __restrict__ attn,
                    const float* __restrict__ ws,
                    float* __restrict__ out, int n) {
    __shared__ float4 tabR[NPL + 1];     // {csum0, w0', csum3, w3'}
    __shared__ float4 tabD[NPL + 1];     // {csum1, w1', csum4, w4'}
    __shared__ float2 tabD6[NPL + 1];    // {csum6, w6'}
    __shared__ float2 tab2[NPL + 1], tab5[NPL + 1], tab7[NPL + 1];
    __shared__ unsigned char s_pb[NITEM + 1], s_pc[NITEM + 1];
    __shared__ float  s_att[WARPS][OBJ];
    __shared__ float4 s_box[WARPS][OBJ];
    __shared__ __align__(8) float s_dT[WARPS][OBJ][DPAD];  // dedup, padded cols
    __shared__ float  s_sim[WARPS][OBJ * OBJ];
    __shared__ float  s_ri[WARPS][OBJ];
    __shared__ float  s_p0[WARPS][OBJ];

    const int tid = threadIdx.x;

    // ---- normalize 8 weight sets into packed fused tables ----
    if (tid < 8) {
        float tmp[NPL + 1];
        float s = 0.0f;
#pragma unroll
        for (int k = 0; k <= NPL; k++) { tmp[k] = fabsf(ws[tid * (NPL + 1) + k]); s += tmp[k]; }
        float inv = 1.0f / s;
        float* bp; int st;
        switch (tid) {
            case 0: bp = &tabR[0].x;  st = 4; break;
            case 3: bp = &tabR[0].z;  st = 4; break;
            case 1: bp = &tabD[0].x;  st = 4; break;
            case 4: bp = &tabD[0].z;  st = 4; break;
            case 6: bp = &tabD6[0].x; st = 2; break;
            case 2: bp = &tab2[0].x;  st = 2; break;
            case 5: bp = &tab5[0].x;  st = 2; break;
            default: bp = &tab7[0].x; st = 2; break;
        }
        float c = 0.0f;
#pragma unroll
        for (int k = 0; k <= NPL; k++) {
            c += tmp[k] * inv;
            int k1 = (k + 1) < NPL ? (k + 1) : NPL;
            bp[k * st]     = c;
            bp[k * st + 1] = tmp[k1] * inv;
        }
    }
    // item map p -> (b,c), b <= c
    if (tid < NITEM) {
        int p = tid, b = 0;
        while (p >= OBJ - b) { p -= OBJ - b; b++; }
        s_pb[tid] = (unsigned char)b;
        s_pc[tid] = (unsigned char)(b + p);
    }
    __syncthreads();

    const int warp = tid >> 5, lane = tid & 31;
    const int row = blockIdx.x * WARPS + warp;
    if (row >= n) return;

    // ---- warp top-10 of 36 via REDUX (exact, low-index tie-break) ----
    unsigned u0 = mapf(attn[row * MOBJ + lane]);
    unsigned u1 = 0;
    if (lane < MOBJ - 32) u1 = mapf(attn[row * MOBJ + 32 + lane]);
    unsigned myval = 0, myidx = 0;
#pragma unroll
    for (int k = 0; k < OBJ; k++) {
        unsigned cand = u0 > u1 ? u0 : u1;
        unsigned m = __reduce_max_sync(0xffffffffu, cand);
        unsigned idx = 0xFFFFFFFFu;
        if (u0 == m) idx = (unsigned)lane;
        if (u1 == m) idx = min(idx, (unsigned)(lane + 32));
        unsigned sel = __reduce_min_sync(0xffffffffu, idx);
        if (sel == (unsigned)lane) u0 = 0;
        else if (sel == (unsigned)(lane + 32)) u1 = 0;
        if (lane == k) { myval = m; myidx = sel; }
    }
    if (lane < OBJ) {
        float v = unmapf(myval);
        float a = __fdividef(1.0f, 1.0f + __expf(-v));
        s_att[warp][lane] = a;
        const float* bb = boxes + (size_t)row * 4 * MOBJ + myidx;
        s_box[warp][lane] = make_float4(bb[0], bb[MOBJ], bb[2 * MOBJ], bb[3 * MOBJ]);
    }
    __syncwarp();

    // ---- pair stage: 55 items (b<=c); shared floors, packed tables ----
    float dconf = 0.0f;
    float sc[2], dav[2];
    int pb[2], pc[2];
#pragma unroll
    for (int r = 0; r < 2; r++) {
        int p = lane + r * 32;
        sc[r] = 0.0f; dav[r] = 0.0f; pb[r] = 0; pc[r] = 0;
        if (p < NITEM) {
            int b = s_pb[p], c = s_pc[p];
            pb[r] = b; pc[r] = c;
            float4 B = s_box[warp][b], C = s_box[warp][c];
            float iw = fmaxf(fminf(B.z, C.z) - fmaxf(B.x, C.x), 0.0f);
            float ih = fmaxf(fminf(B.w, C.w) - fmaxf(B.y, C.y), 0.0f);
            float inter = iw * ih;
            float aa = fmaxf(B.z - B.x, 0.0f) * fmaxf(B.w - B.y, 0.0f);
            float ab = fmaxf(C.z - C.x, 0.0f) * fmaxf(C.w - C.y, 0.0f);
            float dist = fmaxf(1.0f - __fdividef(inter, aa + ab - inter + 1e-12f), 0.0f);
            float atb = s_att[warp][b], atc = s_att[warp][c];
            float relev = atb * atc;
            dav[r] = fabsf(atb - atc);
            int ir; float fr; plfloor(16.0f * relev, ir, fr);
            float4 R = tabR[ir];
            float p0 = fmaf(fr, R.y, R.x);
            float p3 = fmaf(fr, R.w, R.z);
            int id; float fd; plfloor(16.0f * dist, id, fd);
            float4 D = tabD[id];
            float2 D6 = tabD6[id];
            float p1 = fmaf(fd, D.y, D.x);
            float p4 = fmaf(fd, D.w, D.z);
            float p6 = fmaf(fd, D6.y, D6.x);
            sc[r] = p0 * p1;
            float dd = p3 * p4;
            s_dT[warp][b][c] = dd;
            s_dT[warp][c][b] = dd;
            dconf += ((b == c) ? 1.0f : 2.0f) * fabsf(p6 - 0.5f);
            if (b == c) s_p0[warp][b] = p0;
        }
    }
    __syncwarp();

    // ---- sim: 55 items; float2 column reads; diag handled by same code ----
#pragma unroll
    for (int r = 0; r < 2; r++) {
        int p = lane + r * 32;
        if (p < NITEM) {
            int b = pb[r], c = pc[r];
            const float2* db = (const float2*)&s_dT[warp][b][0];
            const float2* dc = (const float2*)&s_dT[warp][c][0];
            float prod = plin2t(tab2, fmaf(-16.0f, dav[r], 16.0f));
#pragma unroll
            for (int a2 = 0; a2 < 5; a2++) {
                float2 x = db[a2], y = dc[a2];
                prod *= plin2t(tab2, fmaf(-16.0f, fabsf(x.x - y.x), 16.0f));
                prod *= plin2t(tab2, fmaf(-16.0f, fabsf(x.y - y.y), 16.0f));
            }
            s_sim[warp][b * OBJ + c] = prod;
            s_sim[warp][c * OBJ + b] = prod;
        }
    }
    __syncwarp();

    // ---- row sims -> reciprocals, correction, aconf ----
    float corr = 0.0f, aconf = 0.0f;
    if (lane < OBJ) {
        float rs = 0.0f;
#pragma unroll
        for (int c = 0; c < OBJ; c++) rs += s_sim[warp][lane * OBJ + c];
        float ri = __fdividef(1.0f, rs);
        s_ri[warp][lane] = ri;
        corr = s_p0[warp][lane] * ri;
        aconf = fabsf(plin2t(tab5, 16.0f * s_att[warp][lane]) - 0.5f);
    }
    __syncwarp();

    // ---- score / all_sims sum (sc held in registers) ----
    float ssum = 0.0f;
#pragma unroll
    for (int r = 0; r < 2; r++) {
        int p = lane + r * 32;
        if (p < NITEM) {
            int b = pb[r], c = pc[r];
            float fac = (b == c) ? 1.0f : 2.0f;
            ssum += fac * sc[r] * s_ri[warp][b] * s_ri[warp][c];
        }
    }

    float tot = sqrtf(warp_sum(ssum + corr) + 1e-20f);
    float confarg = warp_sum(aconf * (1.0f / OBJ) + dconf * (1.0f / (OBJ * OBJ)));
    float conf = plin2t(tab7, 16.0f * confarg);

    // ---- one-hot * conf ----
    float s = fminf(fmaxf(tot, 0.0f), (float)OBJ);
    int ii = (int)s;
    float f = s - (float)ii;
    int oh0 = ii < OBJ ? ii : OBJ;
    int oh1 = (ii + 1) < OBJ ? (ii + 1) : OBJ;
    if (lane < OBJ + 1) {
        float v = 0.0f;
        if (lane == oh0) v += 1.0f - f;
        if (lane == oh1) v += f;
        out[row * (OBJ + 1) + lane] = v * conf;
    }
}

extern "C" void kernel_launch(void* const* d_in, const int* in_sizes, int n_in,
                              void* d_out, int out_size) {
    const float* boxes = (const float*)d_in[0];
    const float* attn  = (const float*)d_in[1];
    const float* ws    = (const float*)d_in[2];
    float* out = (float*)d_out;
    int n = in_sizes[0] / (4 * MOBJ);
    int blocks = (n + WARPS - 1) / WARPS;
    counter_kernel<<<blocks, WARPS * 32>>>(boxes, attn, ws, out, n);
}